// round 12
// baseline (speedup 1.0000x reference)
#include <cuda_runtime.h>
#include <cuda_bf16.h>
#include <math.h>
#include <stdint.h>

#define HH   512
#define BB   256
#define OLEN 512
#define NBLK 128
#define NT   256
#define MB   64          // batch rows per block
#define CB   80          // columns per block: 64 gate (16u x ifgo) + 16 y
#define UPB  16          // hidden units per block

// ---- smem layout (bytes) ----
#define APITCH 144              // 72 bf16 per A row (64 data + 8 pad)
#define ATILE  (64 * APITCH)    // 9216 B per A split tile (64 x 64 k-chunk)
#define NSTAGE 3
#define SM_A   0                // 3 stages x (hi+lo) = 55296 B (gbuf overlays in epilogue)
#define BPITCH 1040             // 520 bf16 per B row (512 data + 8 pad)
#define BSPLIT (80 * BPITCH)    // 83200 B per split
#define SM_B   (NSTAGE * 2 * ATILE)         // 55296
#define SM_C   (SM_B + 2 * BSPLIT)          // 221696 : c-state 16u x 64 rows fp32
#define SM_BIAS (SM_C + UPB * MB * 4)       // 225792 : bias0[80], bias1[80]
#define SM_TOTAL (SM_BIAS + 2 * CB * 4)     // 226432

// ---------------- device scratch ----------------
__device__ float g_Weff[4 * HH * HH];
__device__ float g_Wsum[4 * HH * HH];
__device__ float g_b[4 * HH];
__device__ float g_beff[4 * HH];
__device__ __align__(16) __nv_bfloat16 g_Bimg[32][2][80 * 520];   // steady B (hi,lo)
__device__ __align__(16) __nv_bfloat16 g_B0img[32][2][80 * 520];  // step-0 B
__device__ __align__(16) __nv_bfloat16 g_hA[2][2][BB * HH];       // h images [buf][split][m*512+k]
__device__ __align__(128) unsigned g_bar4[4][32];                 // per-mg-group barrier counters

// ---------------- helpers ----------------
__device__ __forceinline__ uint32_t smem_u32(const void* p) {
    uint32_t a;
    asm("{ .reg .u64 t; cvta.to.shared.u64 t, %1; cvt.u32.u64 %0, t; }" : "=r"(a) : "l"(p));
    return a;
}
__device__ __forceinline__ void mma_bf16(float* d, const uint32_t* a, uint32_t b0, uint32_t b1) {
    asm volatile(
        "mma.sync.aligned.m16n8k16.row.col.f32.bf16.bf16.f32 "
        "{%0,%1,%2,%3}, {%4,%5,%6,%7}, {%8,%9}, {%0,%1,%2,%3};"
        : "+f"(d[0]), "+f"(d[1]), "+f"(d[2]), "+f"(d[3])
        : "r"(a[0]), "r"(a[1]), "r"(a[2]), "r"(a[3]), "r"(b0), "r"(b1));
}
__device__ __forceinline__ void ldsm4(uint32_t* r, uint32_t addr) {
    asm volatile("ldmatrix.sync.aligned.m8n8.x4.shared.b16 {%0,%1,%2,%3}, [%4];"
                 : "=r"(r[0]), "=r"(r[1]), "=r"(r[2]), "=r"(r[3]) : "r"(addr));
}
__device__ __forceinline__ void cpasync16(uint32_t dst, const void* src) {
    asm volatile("cp.async.cg.shared.global [%0], [%1], 16;" :: "r"(dst), "l"(src));
}
__device__ __forceinline__ float sigf(float x) { return 1.f / (1.f + __expf(-x)); }

__device__ __forceinline__ void group_sync(int mg, unsigned target) {
    __syncthreads();
    if (threadIdx.x == 0) {
        __threadfence();
        atomicAdd(&g_bar4[mg][0], 1u);
        while (*(volatile unsigned*)&g_bar4[mg][0] < target) { }
        __threadfence();
    }
    __syncthreads();
}

// ---------------- prologue kernels ----------------
__global__ void k_init() {
    if (threadIdx.x < 4) g_bar4[threadIdx.x][0] = 0u;
}

__global__ void k_prep(const float* __restrict__ Wih, const float* __restrict__ Whh,
                       const float* __restrict__ bih, const float* __restrict__ bhh,
                       const float* __restrict__ blast) {
    int idx = blockIdx.x * blockDim.x + threadIdx.x;
    int nthr = gridDim.x * blockDim.x;
    for (int i = idx; i < 4 * HH * HH; i += nthr)
        g_Wsum[i] = Wih[i] + Whh[i];
    if (idx < 4 * HH) {
        float s = bih[idx] + bhh[idx];
        g_b[idx] = s;
        float acc = 0.f;
        for (int j = 0; j < HH; j++) acc += Wih[idx * HH + j] * blast[j];
        g_beff[idx] = s + acc;
    }
}

__global__ void k_weff(const float* __restrict__ Wih, const float* __restrict__ Whh,
                       const float* __restrict__ Wlast) {
    __shared__ float As[32][32];
    __shared__ float Bs[32][33];
    int r = blockIdx.y * 32 + threadIdx.y;
    int k = blockIdx.x * 32 + threadIdx.x;
    float acc = 0.f;
    for (int j0 = 0; j0 < HH; j0 += 32) {
        As[threadIdx.y][threadIdx.x] = Wih[r * HH + j0 + threadIdx.x];
        Bs[threadIdx.y][threadIdx.x] = Wlast[(j0 + threadIdx.y) * HH + k];
        __syncthreads();
#pragma unroll
        for (int j = 0; j < 32; j++) acc += As[threadIdx.y][j] * Bs[j][threadIdx.x];
        __syncthreads();
    }
    g_Weff[r * HH + k] = acc + Whh[r * HH + k];
}

// pack B images (hi/lo bf16, padded pitch 520) and h0 = z image
__global__ void k_pack(const float* __restrict__ z, const float* __restrict__ Wlast) {
    const int NWI = 32 * 80 * 512;
    int idx = blockIdx.x * blockDim.x + threadIdx.x;
    int nthr = gridDim.x * blockDim.x;
    for (int i = idx; i < 2 * NWI + BB * HH; i += nthr) {
        if (i < 2 * NWI) {
            int which = (i >= NWI) ? 1 : 0;      // 0 = steady (Weff), 1 = step0 (Wsum)
            int j = which ? i - NWI : i;
            int g = j / (80 * 512);
            int r = j % (80 * 512);
            int n = r / 512, k = r % 512;
            float v;
            if (n < 64) {
                int u = n >> 2, q = n & 3;
                const float* W = which ? g_Wsum : g_Weff;
                v = W[(q * HH + 16 * g + u) * HH + k];
            } else {
                v = Wlast[(16 * g + n - 64) * HH + k];
            }
            __nv_bfloat16 hi = __float2bfloat16(v);
            __nv_bfloat16 lo = __float2bfloat16(v - __bfloat162float(hi));
            int o = n * 520 + k;
            if (!which) { g_Bimg[g][0][o] = hi;  g_Bimg[g][1][o] = lo; }
            else        { g_B0img[g][0][o] = hi; g_B0img[g][1][o] = lo; }
        } else {
            int j = i - 2 * NWI;
            float v = z[j];
            __nv_bfloat16 hi = __float2bfloat16(v);
            __nv_bfloat16 lo = __float2bfloat16(v - __bfloat162float(hi));
            g_hA[0][0][j] = hi;
            g_hA[0][1][j] = lo;
        }
    }
}

// ---------------- main persistent kernel ----------------
__device__ __forceinline__ void load_chunk(uint32_t sbase, int stage, int kc, int mg,
                                           const __nv_bfloat16* sH,
                                           const __nv_bfloat16* sL, int tid) {
    uint32_t dbase = sbase + SM_A + stage * (2 * ATILE);
#pragma unroll
    for (int wv = 0; wv < 4; wv++) {
        int i = tid + wv * NT;                  // 0..1023
        int split = i >> 9;
        int j = i & 511;
        int r = j >> 3, c = j & 7;
        const __nv_bfloat16* s = split ? sL : sH;
        const void* src = s + (size_t)(64 * mg + r) * HH + kc * 64 + c * 8;
        uint32_t dst = dbase + split * ATILE + r * APITCH + c * 16;
        cpasync16(dst, src);
    }
    asm volatile("cp.async.commit_group;" ::: "memory");
}

// B via ldmatrix: one ldsm4 covers 8 n-rows x 32 k (two k16 fragments).
__device__ __forceinline__ void compute_chunk(uint32_t sbase, int stage, int kc, float d[5][4],
                                              uint32_t a_lane, uint32_t b_lane) {
    uint32_t A0 = sbase + SM_A + stage * (2 * ATILE) + a_lane;
    uint32_t B0 = sbase + SM_B + b_lane + (uint32_t)kc * 128;
#pragma unroll
    for (int ks2 = 0; ks2 < 2; ks2++) {
        uint32_t aH0[4], aH1[4], aL0[4], aL1[4];
        ldsm4(aH0, A0 + ks2 * 64);
        ldsm4(aH1, A0 + ks2 * 64 + 32);
        ldsm4(aL0, A0 + ATILE + ks2 * 64);
        ldsm4(aL1, A0 + ATILE + ks2 * 64 + 32);
#pragma unroll
        for (int nt = 0; nt < 5; nt++) {
            uint32_t bH[4], bL[4];
            uint32_t ba = B0 + (uint32_t)(nt * 8) * BPITCH + ks2 * 64;
            ldsm4(bH, ba);
            ldsm4(bL, ba + BSPLIT);
            mma_bf16(d[nt], aH0, bH[0], bH[1]);
            mma_bf16(d[nt], aH1, bH[2], bH[3]);
            mma_bf16(d[nt], aH0, bL[0], bL[1]);
            mma_bf16(d[nt], aH1, bL[2], bL[3]);
            mma_bf16(d[nt], aL0, bH[0], bH[1]);
            mma_bf16(d[nt], aL1, bH[2], bH[3]);
        }
    }
}

__global__ void __launch_bounds__(NT, 1)
k_main(const float* __restrict__ z, const float* __restrict__ blast,
       float* __restrict__ out) {
    extern __shared__ unsigned char sm[];
    const int tid = threadIdx.x, w = tid >> 5, lane = tid & 31;
    const int blk = blockIdx.x;
    const int mg = blk >> 5;      // 0..3  (batch group of 64 rows)
    const int g  = blk & 31;      // 0..31 (column group)
    const uint32_t sbase = smem_u32(sm);

    float* c_sm  = (float*)(sm + SM_C);
    float* bias0 = (float*)(sm + SM_BIAS);
    float* bias1 = bias0 + CB;
    float* gbuf  = (float*)(sm + SM_A);   // epilogue overlay on A staging area

    // biases
    if (tid < CB) {
        if (tid < 64) {
            int u = tid >> 2, q = tid & 3;
            int row = q * HH + 16 * g + u;
            bias0[tid] = g_b[row];
            bias1[tid] = g_beff[row];
        } else {
            float v = blast[16 * g + tid - 64];
            bias0[tid] = v; bias1[tid] = v;
        }
    }
    // c0 = z slice for this block's units/rows
    for (int i = tid; i < UPB * MB; i += NT) {
        int u = i & 15, r = i >> 4;
        c_sm[u * MB + r] = z[(size_t)(64 * mg + r) * HH + 16 * g + u];
    }
    // B resident load: step-0 weights
    {
        const float4* s0 = (const float4*)&g_B0img[g][0][0];
        const float4* s1 = (const float4*)&g_B0img[g][1][0];
        float4* d0 = (float4*)(sm + SM_B);
        float4* d1 = (float4*)(sm + SM_B + BSPLIT);
        for (int i = tid; i < BSPLIT / 16; i += NT) { d0[i] = s0[i]; d1[i] = s1[i]; }
    }
    __syncthreads();

    const int mrow  = (w & 3) << 4;      // warp M offset (0,16,32,48)
    const int cbase = (w >> 2) * 40;     // warp col offset (0 or 40)
    const uint32_t a_lane =
        (uint32_t)((mrow + (((lane >> 3) & 1) << 3) + (lane & 7)) * APITCH + (lane >> 4) * 16);
    const uint32_t b_lane =
        (uint32_t)((cbase + (lane & 7)) * BPITCH + (lane >> 3) * 16);

    unsigned gen = 0;

    for (int ss = 0; ss <= OLEN; ss++) {
        const __nv_bfloat16* sH = g_hA[ss & 1][0];
        const __nv_bfloat16* sL = g_hA[ss & 1][1];
        const float* bs = ss ? bias1 : bias0;

        // init accumulators with biases (c2/c3 share columns with c0/c1)
        float d[5][4];
#pragma unroll
        for (int nt = 0; nt < 5; nt++) {
            int col = cbase + nt * 8 + 2 * (lane & 3);
            float b0 = bs[col], b1 = bs[col + 1];
            d[nt][0] = b0; d[nt][1] = b1; d[nt][2] = b0; d[nt][3] = b1;
        }

        // 3-stage cp.async pipeline, one __syncthreads per chunk.
        load_chunk(sbase, 0, 0, mg, sH, sL, tid);
        load_chunk(sbase, 1, 1, mg, sH, sL, tid);
#pragma unroll 1
        for (int kc = 0; kc < 8; kc++) {
            if (kc < 7) asm volatile("cp.async.wait_group 1;" ::: "memory");
            else        asm volatile("cp.async.wait_group 0;" ::: "memory");
            __syncthreads();        // chunk kc visible; all threads done with chunk kc-1
            compute_chunk(sbase, kc % 3, kc, d, a_lane, b_lane);
            if (kc < 6) load_chunk(sbase, (kc + 2) % 3, kc + 2, mg, sH, sL, tid);
        }
        __syncthreads();            // all warps done reading A stages before gbuf overlay

        // ---- epilogue: dump accumulators to gbuf (col-major, pitch 65) ----
        {
            int row = mrow + (lane >> 2);
#pragma unroll
            for (int nt = 0; nt < 5; nt++) {
                int col = cbase + nt * 8 + 2 * (lane & 3);
                gbuf[col * 65 + row]           = d[nt][0];
                gbuf[(col + 1) * 65 + row]     = d[nt][1];
                gbuf[col * 65 + row + 8]       = d[nt][2];
                gbuf[(col + 1) * 65 + row + 8] = d[nt][3];
            }
        }
        __syncthreads();

        {
            const int row = tid >> 2;        // 0..63
            const int ug  = tid & 3;         // unit group of 4
            if (ss < OLEN) {
                __align__(8) __nv_bfloat16 hhi[4], hlo[4];
#pragma unroll
                for (int ii = 0; ii < 4; ii++) {
                    int u = ug * 4 + ii;
                    float iv = gbuf[(4 * u + 0) * 65 + row];
                    float fv = gbuf[(4 * u + 1) * 65 + row];
                    float gv = gbuf[(4 * u + 2) * 65 + row];
                    float ov = gbuf[(4 * u + 3) * 65 + row];
                    float cc = c_sm[u * MB + row];
                    cc = sigf(fv) * cc + sigf(iv) * tanhf(gv);
                    float hv = sigf(ov) * tanhf(cc);
                    c_sm[u * MB + row] = cc;
                    hhi[ii] = __float2bfloat16(hv);
                    hlo[ii] = __float2bfloat16(hv - __bfloat162float(hhi[ii]));
                }
                int dst = (ss + 1) & 1;
                size_t off = (size_t)(64 * mg + row) * HH + 16 * g + 4 * ug;
                *(uint2*)&g_hA[dst][0][off] = *(const uint2*)hhi;
                *(uint2*)&g_hA[dst][1][off] = *(const uint2*)hlo;
            }
            if (ss > 0) {
                float4 y;
                y.x = gbuf[(64 + 4 * ug + 0) * 65 + row];
                y.y = gbuf[(64 + 4 * ug + 1) * 65 + row];
                y.z = gbuf[(64 + 4 * ug + 2) * 65 + row];
                y.w = gbuf[(64 + 4 * ug + 3) * 65 + row];
                *(float4*)&out[(size_t)(64 * mg + row) * OLEN * HH +
                               (size_t)(ss - 1) * HH + 16 * g + 4 * ug] = y;
            }
        }

        if (ss == 0) {
            // swap gate rows (0..63) of B to steady-state W_eff image
            const float4* s0 = (const float4*)&g_Bimg[g][0][0];
            const float4* s1 = (const float4*)&g_Bimg[g][1][0];
            float4* d0 = (float4*)(sm + SM_B);
            float4* d1 = (float4*)(sm + SM_B + BSPLIT);
            for (int i = tid; i < (64 * BPITCH) / 16; i += NT) { d0[i] = s0[i]; d1[i] = s1[i]; }
        }

        // only blocks sharing batch rows (same mg) must synchronize
        if (ss < OLEN) group_sync(mg, ++gen * 32);
    }
}

// ---------------- launch ----------------
extern "C" void kernel_launch(void* const* d_in, const int* in_sizes, int n_in,
                              void* d_out, int out_size) {
    const float* z     = (const float*)d_in[0];
    const float* Wih   = (const float*)d_in[1];
    const float* Whh   = (const float*)d_in[2];
    const float* bih   = (const float*)d_in[3];
    const float* bhh   = (const float*)d_in[4];
    const float* Wlast = (const float*)d_in[5];
    const float* blast = (const float*)d_in[6];
    float* out = (float*)d_out;

    cudaFuncSetAttribute(k_main, cudaFuncAttributeMaxDynamicSharedMemorySize, SM_TOTAL);

    k_init<<<1, 32>>>();
    k_prep<<<4096, 256>>>(Wih, Whh, bih, bhh, blast);
    k_weff<<<dim3(HH / 32, 4 * HH / 32), dim3(32, 32)>>>(Wih, Whh, Wlast);
    k_pack<<<2048, 1024>>>(z, Wlast);
    k_main<<<NBLK, NT, SM_TOTAL>>>(z, blast, out);
}

// round 13
// speedup vs baseline: 1.5371x; 1.5371x over previous
#include <cuda_runtime.h>
#include <cuda_bf16.h>
#include <math.h>
#include <stdint.h>

#define HH   512
#define BB   256
#define OLEN 512
#define NBLK 128
#define NT   256
#define MB   64          // batch rows per block
#define CB   80          // columns per block: 64 gate (16u x ifgo) + 16 y
#define UPB  16          // hidden units per block

// ---- smem layout (bytes) ----
#define APITCH 144              // 72 bf16 per A row (64 data + 8 pad)
#define ATILE  (64 * APITCH)    // 9216 B per A split tile (64 x 64 k-chunk)
#define SM_A   0                // 2 stages x 2 splits = 36864 B (overlaid by gbuf in epilogue)
#define BPITCH 1040             // 520 bf16 per B row (512 data + 8 pad)
#define BSPLIT (80 * BPITCH)    // 83200 B per split
#define SM_B   36864
#define SM_C   (SM_B + 2 * BSPLIT)          // 203264 : c-state 16u x 64 rows fp32
#define SM_BIAS (SM_C + UPB * MB * 4)       // 207360 : bias0[80], bias1[80]
#define SM_TOTAL (SM_BIAS + 2 * CB * 4)     // 208000

// ---------------- device scratch ----------------
__device__ float g_Weff[4 * HH * HH];
__device__ float g_Wsum[4 * HH * HH];
__device__ float g_b[4 * HH];
__device__ float g_beff[4 * HH];
__device__ __align__(16) __nv_bfloat16 g_Bimg[32][2][80 * 520];   // steady B (hi,lo)
__device__ __align__(16) __nv_bfloat16 g_B0img[32][2][80 * 520];  // step-0 B
__device__ __align__(16) __nv_bfloat16 g_hA[2][2][BB * HH];       // h images [buf][split][m*512+k]
__device__ __align__(128) unsigned g_bar4[4][32];                 // per-mg-group barrier counters

// ---------------- helpers ----------------
__device__ __forceinline__ uint32_t smem_u32(const void* p) {
    uint32_t a;
    asm("{ .reg .u64 t; cvta.to.shared.u64 t, %1; cvt.u32.u64 %0, t; }" : "=r"(a) : "l"(p));
    return a;
}
__device__ __forceinline__ void mma_bf16(float* d, const uint32_t* a, uint32_t b0, uint32_t b1) {
    asm volatile(
        "mma.sync.aligned.m16n8k16.row.col.f32.bf16.bf16.f32 "
        "{%0,%1,%2,%3}, {%4,%5,%6,%7}, {%8,%9}, {%0,%1,%2,%3};"
        : "+f"(d[0]), "+f"(d[1]), "+f"(d[2]), "+f"(d[3])
        : "r"(a[0]), "r"(a[1]), "r"(a[2]), "r"(a[3]), "r"(b0), "r"(b1));
}
__device__ __forceinline__ void ldsm4(uint32_t* r, uint32_t addr) {
    asm volatile("ldmatrix.sync.aligned.m8n8.x4.shared.b16 {%0,%1,%2,%3}, [%4];"
                 : "=r"(r[0]), "=r"(r[1]), "=r"(r[2]), "=r"(r[3]) : "r"(addr));
}
__device__ __forceinline__ uint32_t lds32(uint32_t addr) {
    uint32_t v; asm volatile("ld.shared.b32 %0, [%1];" : "=r"(v) : "r"(addr)); return v;
}
__device__ __forceinline__ void cpasync16(uint32_t dst, const void* src) {
    asm volatile("cp.async.cg.shared.global [%0], [%1], 16;" :: "r"(dst), "l"(src));
}
__device__ __forceinline__ float sigf(float x) { return 1.f / (1.f + __expf(-x)); }
// overflow-safe fast tanh: (1 - e^{-2|x|}) / (1 + e^{-2|x|}) with sign restore
__device__ __forceinline__ float tanhf_fast(float x) {
    float t = __expf(-2.f * fabsf(x));
    float r = __fdividef(1.f - t, 1.f + t);
    return copysignf(r, x);
}

// per-mg-group barrier: only the 32 blocks sharing batch rows synchronize
__device__ __forceinline__ void group_sync(int mg, unsigned target) {
    __syncthreads();
    if (threadIdx.x == 0) {
        __threadfence();
        atomicAdd(&g_bar4[mg][0], 1u);
        while (*(volatile unsigned*)&g_bar4[mg][0] < target) { }
        __threadfence();
    }
    __syncthreads();
}

// ---------------- prologue kernels ----------------
__global__ void k_init() {
    if (threadIdx.x < 4) g_bar4[threadIdx.x][0] = 0u;
}

__global__ void k_prep(const float* __restrict__ Wih, const float* __restrict__ Whh,
                       const float* __restrict__ bih, const float* __restrict__ bhh,
                       const float* __restrict__ blast) {
    int idx = blockIdx.x * blockDim.x + threadIdx.x;
    int nthr = gridDim.x * blockDim.x;
    for (int i = idx; i < 4 * HH * HH; i += nthr)
        g_Wsum[i] = Wih[i] + Whh[i];
    if (idx < 4 * HH) {
        float s = bih[idx] + bhh[idx];
        g_b[idx] = s;
        float acc = 0.f;
        for (int j = 0; j < HH; j++) acc += Wih[idx * HH + j] * blast[j];
        g_beff[idx] = s + acc;
    }
}

__global__ void k_weff(const float* __restrict__ Wih, const float* __restrict__ Whh,
                       const float* __restrict__ Wlast) {
    __shared__ float As[32][32];
    __shared__ float Bs[32][33];
    int r = blockIdx.y * 32 + threadIdx.y;
    int k = blockIdx.x * 32 + threadIdx.x;
    float acc = 0.f;
    for (int j0 = 0; j0 < HH; j0 += 32) {
        As[threadIdx.y][threadIdx.x] = Wih[r * HH + j0 + threadIdx.x];
        Bs[threadIdx.y][threadIdx.x] = Wlast[(j0 + threadIdx.y) * HH + k];
        __syncthreads();
#pragma unroll
        for (int j = 0; j < 32; j++) acc += As[threadIdx.y][j] * Bs[j][threadIdx.x];
        __syncthreads();
    }
    g_Weff[r * HH + k] = acc + Whh[r * HH + k];
}

// pack B images (hi/lo bf16, padded pitch 520) and h0 = z image
__global__ void k_pack(const float* __restrict__ z, const float* __restrict__ Wlast) {
    const int NWI = 32 * 80 * 512;
    int idx = blockIdx.x * blockDim.x + threadIdx.x;
    int nthr = gridDim.x * blockDim.x;
    for (int i = idx; i < 2 * NWI + BB * HH; i += nthr) {
        if (i < 2 * NWI) {
            int which = (i >= NWI) ? 1 : 0;      // 0 = steady (Weff), 1 = step0 (Wsum)
            int j = which ? i - NWI : i;
            int g = j / (80 * 512);
            int r = j % (80 * 512);
            int n = r / 512, k = r % 512;
            float v;
            if (n < 64) {
                int u = n >> 2, q = n & 3;
                const float* W = which ? g_Wsum : g_Weff;
                v = W[(q * HH + 16 * g + u) * HH + k];
            } else {
                v = Wlast[(16 * g + n - 64) * HH + k];
            }
            __nv_bfloat16 hi = __float2bfloat16(v);
            __nv_bfloat16 lo = __float2bfloat16(v - __bfloat162float(hi));
            int o = n * 520 + k;
            if (!which) { g_Bimg[g][0][o] = hi;  g_Bimg[g][1][o] = lo; }
            else        { g_B0img[g][0][o] = hi; g_B0img[g][1][o] = lo; }
        } else {
            int j = i - 2 * NWI;
            float v = z[j];
            __nv_bfloat16 hi = __float2bfloat16(v);
            __nv_bfloat16 lo = __float2bfloat16(v - __bfloat162float(hi));
            g_hA[0][0][j] = hi;
            g_hA[0][1][j] = lo;
        }
    }
}

// ---------------- main persistent kernel ----------------
__device__ __forceinline__ void load_chunk(uint32_t sbase, int stage, int kc, int mg,
                                           const __nv_bfloat16* sH,
                                           const __nv_bfloat16* sL, int tid) {
    uint32_t dbase = sbase + SM_A + stage * (2 * ATILE);
#pragma unroll
    for (int wv = 0; wv < 4; wv++) {
        int i = tid + wv * NT;                  // 0..1023
        int split = i >> 9;
        int j = i & 511;
        int r = j >> 3, c = j & 7;
        const __nv_bfloat16* s = split ? sL : sH;
        const void* src = s + (size_t)(64 * mg + r) * HH + kc * 64 + c * 8;
        uint32_t dst = dbase + split * ATILE + r * APITCH + c * 16;
        cpasync16(dst, src);
    }
    asm volatile("cp.async.commit_group;" ::: "memory");
}

// B address includes the k-chunk offset kc*128 bytes (64 k-elements * 2B).
__device__ __forceinline__ void compute_chunk(uint32_t sbase, int stage, int kc, float d[5][4],
                                              uint32_t a_lane, uint32_t b_lane, int cbase) {
    uint32_t A0 = sbase + SM_A + stage * (2 * ATILE) + a_lane;
    uint32_t B0 = sbase + SM_B + b_lane + (uint32_t)cbase * BPITCH + (uint32_t)kc * 128;
#pragma unroll
    for (int ks = 0; ks < 4; ks++) {
        uint32_t aH[4], aL[4];
        ldsm4(aH, A0 + ks * 32);
        ldsm4(aL, A0 + ATILE + ks * 32);
#pragma unroll
        for (int nt = 0; nt < 5; nt++) {
            uint32_t ba = B0 + nt * 8 * BPITCH + ks * 32;
            uint32_t bH0 = lds32(ba), bH1 = lds32(ba + 16);
            uint32_t bL0 = lds32(ba + BSPLIT), bL1 = lds32(ba + BSPLIT + 16);
            mma_bf16(d[nt], aH, bH0, bH1);
            mma_bf16(d[nt], aH, bL0, bL1);
            mma_bf16(d[nt], aL, bH0, bH1);
        }
    }
}

__global__ void __launch_bounds__(NT, 1)
k_main(const float* __restrict__ z, const float* __restrict__ blast,
       float* __restrict__ out) {
    extern __shared__ unsigned char sm[];
    const int tid = threadIdx.x, w = tid >> 5, lane = tid & 31;
    const int blk = blockIdx.x;
    const int mg = blk >> 5;      // 0..3  (batch group of 64 rows)
    const int g  = blk & 31;      // 0..31 (column group)
    const uint32_t sbase = smem_u32(sm);

    float* c_sm  = (float*)(sm + SM_C);
    float* bias0 = (float*)(sm + SM_BIAS);
    float* bias1 = bias0 + CB;
    float* gbuf  = (float*)(sm + SM_A);   // epilogue overlay on A staging area

    // biases
    if (tid < CB) {
        if (tid < 64) {
            int u = tid >> 2, q = tid & 3;
            int row = q * HH + 16 * g + u;
            bias0[tid] = g_b[row];
            bias1[tid] = g_beff[row];
        } else {
            float v = blast[16 * g + tid - 64];
            bias0[tid] = v; bias1[tid] = v;
        }
    }
    // c0 = z slice for this block's units/rows
    for (int i = tid; i < UPB * MB; i += NT) {
        int u = i & 15, r = i >> 4;
        c_sm[u * MB + r] = z[(size_t)(64 * mg + r) * HH + 16 * g + u];
    }
    // B resident load: step-0 weights
    {
        const float4* s0 = (const float4*)&g_B0img[g][0][0];
        const float4* s1 = (const float4*)&g_B0img[g][1][0];
        float4* d0 = (float4*)(sm + SM_B);
        float4* d1 = (float4*)(sm + SM_B + BSPLIT);
        for (int i = tid; i < BSPLIT / 16; i += NT) { d0[i] = s0[i]; d1[i] = s1[i]; }
    }
    __syncthreads();

    const int mrow  = (w & 3) << 4;      // warp M offset (0,16,32,48)
    const int cbase = (w >> 2) * 40;     // warp col offset (0 or 40)
    const uint32_t a_lane =
        (uint32_t)((mrow + (((lane >> 3) & 1) << 3) + (lane & 7)) * APITCH + (lane >> 4) * 16);
    const uint32_t b_lane = (uint32_t)((lane >> 2) * BPITCH + (lane & 3) * 4);

    unsigned gen = 0;

    for (int ss = 0; ss <= OLEN; ss++) {
        const __nv_bfloat16* sH = g_hA[ss & 1][0];
        const __nv_bfloat16* sL = g_hA[ss & 1][1];
        const float* bs = ss ? bias1 : bias0;

        // init accumulators with biases (c2/c3 share columns with c0/c1)
        float d[5][4];
#pragma unroll
        for (int nt = 0; nt < 5; nt++) {
            int col = cbase + nt * 8 + 2 * (lane & 3);
            float b0 = bs[col], b1 = bs[col + 1];
            d[nt][0] = b0; d[nt][1] = b1; d[nt][2] = b0; d[nt][3] = b1;
        }

        load_chunk(sbase, 0, 0, mg, sH, sL, tid);
#pragma unroll 1
        for (int kc = 0; kc < 8; kc++) {
            if (kc < 7) {
                load_chunk(sbase, (kc + 1) & 1, kc + 1, mg, sH, sL, tid);
                asm volatile("cp.async.wait_group 1;" ::: "memory");
            } else {
                asm volatile("cp.async.wait_group 0;" ::: "memory");
            }
            __syncthreads();                 // chunk kc visible to all
            compute_chunk(sbase, kc & 1, kc, d, a_lane, b_lane, cbase);
            __syncthreads();                 // stage consumed before next overwrite
        }

        // ---- epilogue: dump accumulators to gbuf (col-major, pitch 65) ----
        {
            int row = mrow + (lane >> 2);
#pragma unroll
            for (int nt = 0; nt < 5; nt++) {
                int col = cbase + nt * 8 + 2 * (lane & 3);
                gbuf[col * 65 + row]           = d[nt][0];
                gbuf[(col + 1) * 65 + row]     = d[nt][1];
                gbuf[col * 65 + row + 8]       = d[nt][2];
                gbuf[(col + 1) * 65 + row + 8] = d[nt][3];
            }
        }
        __syncthreads();

        {
            const int row = tid >> 2;        // 0..63
            const int ug  = tid & 3;         // unit group of 4
            if (ss < OLEN) {
                __align__(8) __nv_bfloat16 hhi[4], hlo[4];
#pragma unroll
                for (int ii = 0; ii < 4; ii++) {
                    int u = ug * 4 + ii;
                    float iv = gbuf[(4 * u + 0) * 65 + row];
                    float fv = gbuf[(4 * u + 1) * 65 + row];
                    float gv = gbuf[(4 * u + 2) * 65 + row];
                    float ov = gbuf[(4 * u + 3) * 65 + row];
                    float cc = c_sm[u * MB + row];
                    cc = sigf(fv) * cc + sigf(iv) * tanhf_fast(gv);
                    float hv = sigf(ov) * tanhf_fast(cc);
                    c_sm[u * MB + row] = cc;
                    hhi[ii] = __float2bfloat16(hv);
                    hlo[ii] = __float2bfloat16(hv - __bfloat162float(hhi[ii]));
                }
                int dst = (ss + 1) & 1;
                size_t off = (size_t)(64 * mg + row) * HH + 16 * g + 4 * ug;
                *(uint2*)&g_hA[dst][0][off] = *(const uint2*)hhi;
                *(uint2*)&g_hA[dst][1][off] = *(const uint2*)hlo;
            }
            if (ss > 0) {
                float4 y;
                y.x = gbuf[(64 + 4 * ug + 0) * 65 + row];
                y.y = gbuf[(64 + 4 * ug + 1) * 65 + row];
                y.z = gbuf[(64 + 4 * ug + 2) * 65 + row];
                y.w = gbuf[(64 + 4 * ug + 3) * 65 + row];
                *(float4*)&out[(size_t)(64 * mg + row) * OLEN * HH +
                               (size_t)(ss - 1) * HH + 16 * g + 4 * ug] = y;
            }
        }

        if (ss == 0) {
            // swap gate rows (0..63) of B to steady-state W_eff image
            const float4* s0 = (const float4*)&g_Bimg[g][0][0];
            const float4* s1 = (const float4*)&g_Bimg[g][1][0];
            float4* d0 = (float4*)(sm + SM_B);
            float4* d1 = (float4*)(sm + SM_B + BSPLIT);
            for (int i = tid; i < (64 * BPITCH) / 16; i += NT) { d0[i] = s0[i]; d1[i] = s1[i]; }
        }

        // only the 32 blocks sharing batch rows (same mg) must synchronize
        if (ss < OLEN) group_sync(mg, ++gen * 32);
    }
}

// ---------------- launch ----------------
extern "C" void kernel_launch(void* const* d_in, const int* in_sizes, int n_in,
                              void* d_out, int out_size) {
    const float* z     = (const float*)d_in[0];
    const float* Wih   = (const float*)d_in[1];
    const float* Whh   = (const float*)d_in[2];
    const float* bih   = (const float*)d_in[3];
    const float* bhh   = (const float*)d_in[4];
    const float* Wlast = (const float*)d_in[5];
    const float* blast = (const float*)d_in[6];
    float* out = (float*)d_out;

    cudaFuncSetAttribute(k_main, cudaFuncAttributeMaxDynamicSharedMemorySize, SM_TOTAL);

    k_init<<<1, 32>>>();
    k_prep<<<4096, 256>>>(Wih, Whh, bih, bhh, blast);
    k_weff<<<dim3(HH / 32, 4 * HH / 32), dim3(32, 32)>>>(Wih, Whh, Wlast);
    k_pack<<<2048, 1024>>>(z, Wlast);
    k_main<<<NBLK, NT, SM_TOTAL>>>(z, blast, out);
}